// round 1
// baseline (speedup 1.0000x reference)
#include <cuda_runtime.h>
#include <math.h>

#define NN    50000
#define DIMF  128
#define NH    8
#define HD    16
#define EE    800000
#define NRELC 2000
#define TT    200000
#define RRULE 50000
#define BB    10000
#define TV_INV 0.029462782549439483f   // 1/(3*sqrt(128))

// ---------------- device scratch (static, no runtime allocation) -------------
__device__ __align__(16) float    d_x[NN * DIMF];      // current node features
__device__ __align__(16) float    d_h[NN * DIMF];      // h = x @ W
__device__ __align__(16) float    d_msg[NN * DIMF];    // message accumulator
__device__ float                  d_asrc[NN * NH];
__device__ float                  d_adst[NN * NH];
__device__ unsigned int           d_menc[NN * NH];     // encoded segment max
__device__ float                  d_den[NN * NH];      // softmax denominator
__device__ float                  d_e[EE * NH];        // per-edge logits
__device__ __align__(16) float    d_feat[NN * DIMF];   // final GAT output (unnormalized)
__device__ __align__(16) float    d_gnorm[NN * DIMF];  // l2-normalized nodes
__device__ __align__(16) float    d_rnorm[NRELC * DIMF]; // l2-normalized relations

// order-preserving float<->uint for atomicMax
__device__ __forceinline__ unsigned int enc_f(float f) {
    unsigned int u = __float_as_uint(f);
    return (u & 0x80000000u) ? ~u : (u | 0x80000000u);
}
__device__ __forceinline__ float dec_f(unsigned int u) {
    return (u & 0x80000000u) ? __uint_as_float(u ^ 0x80000000u) : __uint_as_float(~u);
}

// ---------------- kernels ----------------------------------------------------

__global__ void k_copy(const float* __restrict__ src) {
    int i = blockIdx.x * blockDim.x + threadIdx.x;
    if (i < NN * DIMF) d_x[i] = src[i];
}

__global__ void k_init() {
    int i = blockIdx.x * blockDim.x + threadIdx.x;
    if (i < NN * DIMF) d_msg[i] = 0.0f;
    if (i < NN * NH) {
        d_menc[i] = enc_f(-INFINITY);   // 0x007FFFFF
        d_den[i]  = 0.0f;
    }
}

// one block (128 threads) per node: h = x @ W, plus per-head attention scalars
__global__ void __launch_bounds__(128) k_gemm_alpha(
    const float* __restrict__ W,      // [128,128] (d, h*k)
    const float* __restrict__ a_s,    // [128]
    const float* __restrict__ a_d)    // [128]
{
    int n = blockIdx.x;
    int t = threadIdx.x;               // output channel (head*16 + k)
    __shared__ float xs[DIMF];
    xs[t] = d_x[n * DIMF + t];
    __syncthreads();

    float acc = 0.0f;
#pragma unroll 8
    for (int d = 0; d < DIMF; d++)
        acc = fmaf(xs[d], W[d * DIMF + t], acc);
    d_h[n * DIMF + t] = acc;

    float v1 = acc * a_s[t];
    float v2 = acc * a_d[t];
#pragma unroll
    for (int o = 8; o > 0; o >>= 1) {
        v1 += __shfl_down_sync(0xffffffffu, v1, o, 16);
        v2 += __shfl_down_sync(0xffffffffu, v2, o, 16);
    }
    if ((t & 15) == 0) {
        int head = t >> 4;
        d_asrc[n * NH + head] = v1;
        d_adst[n * NH + head] = v2;
    }
}

// pass 1: leaky_relu logits + segment max (thread per edge*head)
__global__ void k_edge_max(const int* __restrict__ src, const int* __restrict__ dst) {
    int i = blockIdx.x * blockDim.x + threadIdx.x;
    if (i >= EE * NH) return;
    int e = i >> 3, h = i & 7;
    int s = src[e], d = dst[e];
    float v = d_asrc[s * NH + h] + d_adst[d * NH + h];
    v = (v >= 0.0f) ? v : 0.2f * v;
    d_e[i] = v;
    atomicMax(&d_menc[d * NH + h], enc_f(v));
}

// pass 2: w = exp(e - m), accumulate denom + messages (warp per edge)
__global__ void __launch_bounds__(256) k_edge_acc(const int* __restrict__ src,
                                                  const int* __restrict__ dst) {
    int gt = blockIdx.x * blockDim.x + threadIdx.x;
    int e = gt >> 5, lane = gt & 31;
    if (e >= EE) return;
    int s = src[e], d = dst[e];

    float w = 0.0f;
    if (lane < NH) {
        float m = dec_f(d_menc[d * NH + lane]);
        if (!isfinite(m)) m = 0.0f;
        w = expf(d_e[e * NH + lane] - m);
        atomicAdd(&d_den[d * NH + lane], w);
    }
#pragma unroll
    for (int j = 0; j < 4; j++) {
        int c = lane + 32 * j;
        float wv = __shfl_sync(0xffffffffu, w, c >> 4);
        atomicAdd(&d_msg[d * DIMF + c], wv * d_h[s * DIMF + c]);
    }
}

// out = msg / max(denom,1e-16); ELU between layers, raw at last layer
__global__ void k_final(int last) {
    int i = blockIdx.x * blockDim.x + threadIdx.x;
    if (i >= NN * DIMF) return;
    int n = i >> 7, c = i & 127, h = c >> 4;
    float v = d_msg[i] / fmaxf(d_den[n * NH + h], 1e-16f);
    if (last) d_feat[i] = v;
    else      d_x[i] = (v > 0.0f) ? v : expm1f(v);
}

// warp-per-row l2 normalization of d_feat -> d_gnorm
__global__ void k_norm_nodes() {
    int gt = blockIdx.x * blockDim.x + threadIdx.x;
    int row = gt >> 5, lane = gt & 31;
    if (row >= NN) return;
    float4 v = reinterpret_cast<const float4*>(d_feat + (size_t)row * DIMF)[lane];
    float s = v.x * v.x + v.y * v.y + v.z * v.z + v.w * v.w;
#pragma unroll
    for (int o = 16; o > 0; o >>= 1) s += __shfl_xor_sync(0xffffffffu, s, o);
    float sc = 1.0f / fmaxf(sqrtf(s), 1e-12f);
    v.x *= sc; v.y *= sc; v.z *= sc; v.w *= sc;
    reinterpret_cast<float4*>(d_gnorm + (size_t)row * DIMF)[lane] = v;
}

__global__ void k_norm_rel(const float* __restrict__ rel) {
    int gt = blockIdx.x * blockDim.x + threadIdx.x;
    int row = gt >> 5, lane = gt & 31;
    if (row >= NRELC) return;
    float4 v = reinterpret_cast<const float4*>(rel + (size_t)row * DIMF)[lane];
    float s = v.x * v.x + v.y * v.y + v.z * v.z + v.w * v.w;
#pragma unroll
    for (int o = 16; o > 0; o >>= 1) s += __shfl_xor_sync(0xffffffffu, s, o);
    float sc = 1.0f / fmaxf(sqrtf(s), 1e-12f);
    v.x *= sc; v.y *= sc; v.z *= sc; v.w *= sc;
    reinterpret_cast<float4*>(d_rnorm + (size_t)row * DIMF)[lane] = v;
}

__device__ __forceinline__ float transe_tv_warp(int hh, int tt, int rr, int lane) {
    float4 a = reinterpret_cast<const float4*>(d_gnorm + (size_t)hh * DIMF)[lane];
    float4 b = reinterpret_cast<const float4*>(d_rnorm + (size_t)rr * DIMF)[lane];
    float4 c = reinterpret_cast<const float4*>(d_gnorm + (size_t)tt * DIMF)[lane];
    float s = fabsf(a.x + b.x - c.x) + fabsf(a.y + b.y - c.y) +
              fabsf(a.z + b.z - c.z) + fabsf(a.w + b.w - c.w);
#pragma unroll
    for (int o = 16; o > 0; o >>= 1) s += __shfl_down_sync(0xffffffffu, s, o);
    return 1.0f - s * TV_INV;
}

// warp per (triple,col); count = 2*T
__global__ void __launch_bounds__(256) k_transe(const int* __restrict__ hI,
                                                const int* __restrict__ tI,
                                                const int* __restrict__ rI,
                                                float* __restrict__ out, int count) {
    int gt = blockIdx.x * blockDim.x + threadIdx.x;
    int w = gt >> 5, lane = gt & 31;
    if (w >= count) return;
    float tv = transe_tv_warp(hI[w], tI[w], rI[w], lane);
    if (lane == 0) out[w] = tv;
}

// warp per rule row
__global__ void __launch_bounds__(256) k_rule(const int* __restrict__ rh,
                                              const int* __restrict__ rt,
                                              const int* __restrict__ rr,
                                              const int* __restrict__ prem,
                                              const float* __restrict__ tv, int col,
                                              float* __restrict__ out) {
    int gt = blockIdx.x * blockDim.x + threadIdx.x;
    int w = gt >> 5, lane = gt & 31;
    if (w >= RRULE) return;
    float rs = transe_tv_warp(rh[w], rt[w], rr[w], lane);
    if (lane == 0) {
        int p0 = prem[w * 2 + 0];
        int p1 = prem[w * 2 + 1];
        float f1 = (p0 < TT) ? tv[p0 * 2 + col] : 1.0f;
        float f2 = (p1 < TT) ? tv[p1 * 2 + col] : 1.0f;
        out[w] = 1.0f + f1 * f2 * (rs - 1.0f);
    }
}

__global__ void k_gather(const int* __restrict__ idx, float* __restrict__ out) {
    int i = blockIdx.x * blockDim.x + threadIdx.x;
    if (i >= BB * DIMF) return;
    int b = i >> 7, c = i & 127;
    out[i] = d_feat[(size_t)idx[b] * DIMF + c];
}

// ---------------- host orchestration ----------------------------------------
static inline int nblk(long n, int t) { return (int)((n + t - 1) / t); }

extern "C" void kernel_launch(void* const* d_in, const int* in_sizes, int n_in,
                              void* d_out, int out_size) {
    const float* ent[2]  = {(const float*)d_in[0], (const float*)d_in[1]};
    const float* rel[2]  = {(const float*)d_in[2], (const float*)d_in[3]};
    const float* W       = (const float*)d_in[4];   // [2,128,8,16]
    const float* a_s     = (const float*)d_in[5];   // [2,8,16]
    const float* a_d     = (const float*)d_in[6];
    const int* dat[2]    = {(const int*)d_in[7],  (const int*)d_in[8]};
    const int* edg[2]    = {(const int*)d_in[9],  (const int*)d_in[10]};
    const int* hI[2]     = {(const int*)d_in[11], (const int*)d_in[14]};
    const int* tI[2]     = {(const int*)d_in[12], (const int*)d_in[15]};
    const int* rI[2]     = {(const int*)d_in[13], (const int*)d_in[16]};
    const int* rhI[2]    = {(const int*)d_in[17], (const int*)d_in[21]};
    const int* rtI[2]    = {(const int*)d_in[18], (const int*)d_in[22]};
    const int* rrI[2]    = {(const int*)d_in[19], (const int*)d_in[23]};
    const int* prem[2]   = {(const int*)d_in[20], (const int*)d_in[24]};

    float* out      = (float*)d_out;
    float* out_feat[2] = {out, out + (size_t)BB * DIMF};
    float* out_tv   = out + 2 * (size_t)BB * DIMF;          // [2T,2] sr then [2T... tg]
    float* out_rule = out_tv + 4 * (size_t)TT;              // [2R,1]

    for (int g = 0; g < 2; g++) {
        const int* src = edg[g];
        const int* dst = edg[g] + EE;

        k_copy<<<nblk((long)NN * DIMF, 256), 256>>>(ent[g]);

        for (int l = 0; l < 2; l++) {
            k_init<<<nblk((long)NN * DIMF, 256), 256>>>();
            k_gemm_alpha<<<NN, 128>>>(W + (size_t)l * DIMF * DIMF,
                                      a_s + (size_t)l * DIMF,
                                      a_d + (size_t)l * DIMF);
            k_edge_max<<<nblk((long)EE * NH, 256), 256>>>(src, dst);
            k_edge_acc<<<nblk((long)EE * 32, 256), 256>>>(src, dst);
            k_final<<<nblk((long)NN * DIMF, 256), 256>>>(l == 1 ? 1 : 0);
        }

        k_norm_nodes<<<nblk((long)NN * 32, 256), 256>>>();
        k_norm_rel<<<nblk((long)NRELC * 32, 256), 256>>>(rel[g]);

        k_transe<<<nblk((long)2 * TT * 32, 256), 256>>>(hI[g], tI[g], rI[g],
                                                        out_tv + (size_t)g * 2 * TT, 2 * TT);
        k_rule<<<nblk((long)RRULE * 32, 256), 256>>>(rhI[g], rtI[g], rrI[g], prem[g],
                                                     out_tv + (size_t)g * 2 * TT, g,
                                                     out_rule + (size_t)g * RRULE);
        k_gather<<<nblk((long)BB * DIMF, 256), 256>>>(dat[g], out_feat[g]);
    }
    (void)in_sizes; (void)n_in; (void)out_size;
}

// round 2
// speedup vs baseline: 1.6801x; 1.6801x over previous
#include <cuda_runtime.h>
#include <math.h>

#define NN    50000
#define DIMF  128
#define NH    8
#define HD    16
#define EE    800000
#define NRELC 2000
#define TT    200000
#define RRULE 50000
#define BB    10000
#define NPB   8
#define TV_INV 0.029462782549439483f   // 1/(3*sqrt(128))

// ---------------- device scratch (static, no runtime allocation) -------------
__device__ __align__(16) float    d_x[NN * DIMF];      // current node features
__device__ __align__(16) float    d_h[NN * DIMF];      // h = x @ W
__device__ float                  d_asrc[NN * NH];
__device__ float                  d_adst[NN * NH];
__device__ __align__(16) float    d_feat[NN * DIMF];   // final GAT output (unnormalized)
__device__ __align__(16) float    d_gnorm[NN * DIMF];  // l2-normalized nodes
__device__ __align__(16) float    d_rnorm[NRELC * DIMF];
// CSR scratch
__device__ int d_cnt[NN];
__device__ int d_off[NN + 1];
__device__ int d_cur[NN];
__device__ int d_csrc[EE];

// ---------------- f32x2 packed helpers ---------------------------------------
__device__ __forceinline__ unsigned long long pack2(float x, float y) {
    unsigned long long r;
    asm("mov.b64 %0, {%1, %2};" : "=l"(r) : "f"(x), "f"(y));
    return r;
}
__device__ __forceinline__ void unpack2(unsigned long long v, float& x, float& y) {
    asm("mov.b64 {%0, %1}, %2;" : "=f"(x), "=f"(y) : "l"(v));
}
__device__ __forceinline__ unsigned long long fma2(unsigned long long a,
                                                   unsigned long long b,
                                                   unsigned long long c) {
    unsigned long long r;
    asm("fma.rn.f32x2 %0, %1, %2, %3;" : "=l"(r) : "l"(a), "l"(b), "l"(c));
    return r;
}

// ---------------- kernels ----------------------------------------------------

__global__ void k_copy(const float* __restrict__ src) {
    int i = blockIdx.x * blockDim.x + threadIdx.x;
    if (i < NN * DIMF) d_x[i] = src[i];
}

// ---- CSR build ----
__global__ void k_zero_cnt() {
    int i = blockIdx.x * blockDim.x + threadIdx.x;
    if (i < NN) d_cnt[i] = 0;
}
__global__ void k_hist(const int* __restrict__ dst) {
    int i = blockIdx.x * blockDim.x + threadIdx.x;
    if (i < EE) atomicAdd(&d_cnt[dst[i]], 1);
}
#define SCAN_CH 49
__global__ void __launch_bounds__(1024) k_scan() {
    __shared__ int ps[1024];
    int t = threadIdx.x;
    int base = t * SCAN_CH;
    int s = 0;
#pragma unroll 7
    for (int k = 0; k < SCAN_CH; k++) {
        int i = base + k;
        if (i < NN) s += d_cnt[i];
    }
    ps[t] = s;
    __syncthreads();
    for (int o = 1; o < 1024; o <<= 1) {
        int v = (t >= o) ? ps[t - o] : 0;
        __syncthreads();
        ps[t] += v;
        __syncthreads();
    }
    int run = (t > 0) ? ps[t - 1] : 0;
    for (int k = 0; k < SCAN_CH; k++) {
        int i = base + k;
        if (i < NN) {
            d_off[i] = run;
            d_cur[i] = run;
            run += d_cnt[i];
        }
    }
    if (t == 1023) d_off[NN] = EE;
}
__global__ void k_scatter(const int* __restrict__ src, const int* __restrict__ dst) {
    int i = blockIdx.x * blockDim.x + threadIdx.x;
    if (i >= EE) return;
    int d = dst[i];
    int p = atomicAdd(&d_cur[d], 1);
    d_csrc[p] = src[i];
}

// ---- GEMM: h = x @ W, 8 nodes per block, f32x2 packed accumulation ----
__global__ void __launch_bounds__(128) k_gemm8(const float* __restrict__ W) {
    __shared__ float xst[DIMF][NPB];   // transposed: [d][node]
    int nb = blockIdx.x * NPB;
    int t = threadIdx.x;

    for (int k = t; k < NPB * DIMF; k += 128) {
        int u = k >> 7, d = k & 127;
        xst[d][u] = d_x[(size_t)(nb + u) * DIMF + d];
    }
    __syncthreads();

    unsigned long long a01 = 0ull, a23 = 0ull, a45 = 0ull, a67 = 0ull;
#pragma unroll 8
    for (int d = 0; d < DIMF; d++) {
        float w = __ldg(W + d * DIMF + t);
        unsigned long long w2 = pack2(w, w);
        const unsigned long long* xr =
            reinterpret_cast<const unsigned long long*>(&xst[d][0]);
        a01 = fma2(xr[0], w2, a01);
        a23 = fma2(xr[1], w2, a23);
        a45 = fma2(xr[2], w2, a45);
        a67 = fma2(xr[3], w2, a67);
    }
    float v[NPB];
    unpack2(a01, v[0], v[1]);
    unpack2(a23, v[2], v[3]);
    unpack2(a45, v[4], v[5]);
    unpack2(a67, v[6], v[7]);
#pragma unroll
    for (int u = 0; u < NPB; u++)
        d_h[(size_t)(nb + u) * DIMF + t] = v[u];
}

// ---- attention scalars: warp per node ----
__global__ void __launch_bounds__(256) k_alpha(const float* __restrict__ a_s,
                                               const float* __restrict__ a_d) {
    int gt = blockIdx.x * blockDim.x + threadIdx.x;
    int n = gt >> 5, lane = gt & 31;
    if (n >= NN) return;
    float4 h4 = reinterpret_cast<const float4*>(d_h + (size_t)n * DIMF)[lane];
    float4 as = reinterpret_cast<const float4*>(a_s)[lane];
    float4 ad = reinterpret_cast<const float4*>(a_d)[lane];
    float v1 = h4.x * as.x + h4.y * as.y + h4.z * as.z + h4.w * as.w;
    float v2 = h4.x * ad.x + h4.y * ad.y + h4.z * ad.z + h4.w * ad.w;
    v1 += __shfl_down_sync(0xffffffffu, v1, 2, 4);
    v2 += __shfl_down_sync(0xffffffffu, v2, 2, 4);
    v1 += __shfl_down_sync(0xffffffffu, v1, 1, 4);
    v2 += __shfl_down_sync(0xffffffffu, v2, 1, 4);
    if ((lane & 3) == 0) {
        int head = lane >> 2;
        d_asrc[n * NH + head] = v1;
        d_adst[n * NH + head] = v2;
    }
}

// ---- fused softmax-aggregate: warp per dst node, no atomics ----
__global__ void __launch_bounds__(256) k_agg(int last) {
    int gt = blockIdx.x * blockDim.x + threadIdx.x;
    int n = gt >> 5, lane = gt & 31;
    if (n >= NN) return;
    int beg = d_off[n], end = d_off[n + 1];
    int head = lane >> 2;

    float adst_l = (lane < NH) ? d_adst[n * NH + lane] : 0.0f;

    // pass 1: per-head max (lanes 0..7)
    float m = -INFINITY;
    for (int j = beg; j < end; j++) {
        int s = __ldg(&d_csrc[j]);
        if (lane < NH) {
            float v = d_asrc[s * NH + lane] + adst_l;
            v = fmaxf(v, 0.2f * v);        // leaky_relu(0.2)
            m = fmaxf(m, v);
        }
    }

    // pass 2: accumulate
    float4 acc = make_float4(0.f, 0.f, 0.f, 0.f);
    float den = 0.0f;
    int s = (beg < end) ? __ldg(&d_csrc[beg]) : 0;
    for (int j = beg; j < end; j++) {
        int snext = (j + 1 < end) ? __ldg(&d_csrc[j + 1]) : 0;
        float wv = 0.0f;
        if (lane < NH) {
            float v = d_asrc[s * NH + lane] + adst_l;
            v = fmaxf(v, 0.2f * v);
            wv = expf(v - m);
            den += wv;
        }
        float wb = __shfl_sync(0xffffffffu, wv, head);
        float4 hv = reinterpret_cast<const float4*>(d_h + (size_t)s * DIMF)[lane];
        acc.x += wb * hv.x;
        acc.y += wb * hv.y;
        acc.z += wb * hv.z;
        acc.w += wb * hv.w;
        s = snext;
    }
    float denb = __shfl_sync(0xffffffffu, den, head);
    float inv = 1.0f / fmaxf(denb, 1e-16f);
    acc.x *= inv; acc.y *= inv; acc.z *= inv; acc.w *= inv;

    if (last) {
        reinterpret_cast<float4*>(d_feat + (size_t)n * DIMF)[lane] = acc;
    } else {
        acc.x = (acc.x > 0.f) ? acc.x : expm1f(acc.x);
        acc.y = (acc.y > 0.f) ? acc.y : expm1f(acc.y);
        acc.z = (acc.z > 0.f) ? acc.z : expm1f(acc.z);
        acc.w = (acc.w > 0.f) ? acc.w : expm1f(acc.w);
        reinterpret_cast<float4*>(d_x + (size_t)n * DIMF)[lane] = acc;
    }
}

// ---- l2 normalization ----
__global__ void k_norm_nodes() {
    int gt = blockIdx.x * blockDim.x + threadIdx.x;
    int row = gt >> 5, lane = gt & 31;
    if (row >= NN) return;
    float4 v = reinterpret_cast<const float4*>(d_feat + (size_t)row * DIMF)[lane];
    float s = v.x * v.x + v.y * v.y + v.z * v.z + v.w * v.w;
#pragma unroll
    for (int o = 16; o > 0; o >>= 1) s += __shfl_xor_sync(0xffffffffu, s, o);
    float sc = 1.0f / fmaxf(sqrtf(s), 1e-12f);
    v.x *= sc; v.y *= sc; v.z *= sc; v.w *= sc;
    reinterpret_cast<float4*>(d_gnorm + (size_t)row * DIMF)[lane] = v;
}

__global__ void k_norm_rel(const float* __restrict__ rel) {
    int gt = blockIdx.x * blockDim.x + threadIdx.x;
    int row = gt >> 5, lane = gt & 31;
    if (row >= NRELC) return;
    float4 v = reinterpret_cast<const float4*>(rel + (size_t)row * DIMF)[lane];
    float s = v.x * v.x + v.y * v.y + v.z * v.z + v.w * v.w;
#pragma unroll
    for (int o = 16; o > 0; o >>= 1) s += __shfl_xor_sync(0xffffffffu, s, o);
    float sc = 1.0f / fmaxf(sqrtf(s), 1e-12f);
    v.x *= sc; v.y *= sc; v.z *= sc; v.w *= sc;
    reinterpret_cast<float4*>(d_rnorm + (size_t)row * DIMF)[lane] = v;
}

__device__ __forceinline__ float transe_tv_warp(int hh, int tt, int rr, int lane) {
    float4 a = reinterpret_cast<const float4*>(d_gnorm + (size_t)hh * DIMF)[lane];
    float4 b = reinterpret_cast<const float4*>(d_rnorm + (size_t)rr * DIMF)[lane];
    float4 c = reinterpret_cast<const float4*>(d_gnorm + (size_t)tt * DIMF)[lane];
    float s = fabsf(a.x + b.x - c.x) + fabsf(a.y + b.y - c.y) +
              fabsf(a.z + b.z - c.z) + fabsf(a.w + b.w - c.w);
#pragma unroll
    for (int o = 16; o > 0; o >>= 1) s += __shfl_down_sync(0xffffffffu, s, o);
    return 1.0f - s * TV_INV;
}

__global__ void __launch_bounds__(256) k_transe(const int* __restrict__ hI,
                                                const int* __restrict__ tI,
                                                const int* __restrict__ rI,
                                                float* __restrict__ out, int count) {
    int gt = blockIdx.x * blockDim.x + threadIdx.x;
    int w = gt >> 5, lane = gt & 31;
    if (w >= count) return;
    float tv = transe_tv_warp(hI[w], tI[w], rI[w], lane);
    if (lane == 0) out[w] = tv;
}

__global__ void __launch_bounds__(256) k_rule(const int* __restrict__ rh,
                                              const int* __restrict__ rt,
                                              const int* __restrict__ rr,
                                              const int* __restrict__ prem,
                                              const float* __restrict__ tv, int col,
                                              float* __restrict__ out) {
    int gt = blockIdx.x * blockDim.x + threadIdx.x;
    int w = gt >> 5, lane = gt & 31;
    if (w >= RRULE) return;
    float rs = transe_tv_warp(rh[w], rt[w], rr[w], lane);
    if (lane == 0) {
        int p0 = prem[w * 2 + 0];
        int p1 = prem[w * 2 + 1];
        float f1 = (p0 < TT) ? tv[p0 * 2 + col] : 1.0f;
        float f2 = (p1 < TT) ? tv[p1 * 2 + col] : 1.0f;
        out[w] = 1.0f + f1 * f2 * (rs - 1.0f);
    }
}

__global__ void k_gather(const int* __restrict__ idx, float* __restrict__ out) {
    int i = blockIdx.x * blockDim.x + threadIdx.x;
    if (i >= BB * DIMF) return;
    int b = i >> 7, c = i & 127;
    out[i] = d_feat[(size_t)idx[b] * DIMF + c];
}

// ---------------- host orchestration ----------------------------------------
static inline int nblk(long n, int t) { return (int)((n + t - 1) / t); }

extern "C" void kernel_launch(void* const* d_in, const int* in_sizes, int n_in,
                              void* d_out, int out_size) {
    const float* ent[2]  = {(const float*)d_in[0], (const float*)d_in[1]};
    const float* rel[2]  = {(const float*)d_in[2], (const float*)d_in[3]};
    const float* W       = (const float*)d_in[4];   // [2,128,8,16]
    const float* a_s     = (const float*)d_in[5];   // [2,8,16]
    const float* a_d     = (const float*)d_in[6];
    const int* dat[2]    = {(const int*)d_in[7],  (const int*)d_in[8]};
    const int* edg[2]    = {(const int*)d_in[9],  (const int*)d_in[10]};
    const int* hI[2]     = {(const int*)d_in[11], (const int*)d_in[14]};
    const int* tI[2]     = {(const int*)d_in[12], (const int*)d_in[15]};
    const int* rI[2]     = {(const int*)d_in[13], (const int*)d_in[16]};
    const int* rhI[2]    = {(const int*)d_in[17], (const int*)d_in[21]};
    const int* rtI[2]    = {(const int*)d_in[18], (const int*)d_in[22]};
    const int* rrI[2]    = {(const int*)d_in[19], (const int*)d_in[23]};
    const int* prem[2]   = {(const int*)d_in[20], (const int*)d_in[24]};

    float* out      = (float*)d_out;
    float* out_feat[2] = {out, out + (size_t)BB * DIMF};
    float* out_tv   = out + 2 * (size_t)BB * DIMF;
    float* out_rule = out_tv + 4 * (size_t)TT;

    for (int g = 0; g < 2; g++) {
        const int* src = edg[g];
        const int* dst = edg[g] + EE;

        // CSR build (per graph, reused by both layers)
        k_zero_cnt<<<nblk(NN, 256), 256>>>();
        k_hist<<<nblk(EE, 256), 256>>>(dst);
        k_scan<<<1, 1024>>>();
        k_scatter<<<nblk(EE, 256), 256>>>(src, dst);

        k_copy<<<nblk((long)NN * DIMF, 256), 256>>>(ent[g]);

        for (int l = 0; l < 2; l++) {
            k_gemm8<<<NN / NPB, 128>>>(W + (size_t)l * DIMF * DIMF);
            k_alpha<<<nblk((long)NN * 32, 256), 256>>>(a_s + (size_t)l * DIMF,
                                                       a_d + (size_t)l * DIMF);
            k_agg<<<nblk((long)NN * 32, 256), 256>>>(l == 1 ? 1 : 0);
        }

        k_norm_nodes<<<nblk((long)NN * 32, 256), 256>>>();
        k_norm_rel<<<nblk((long)NRELC * 32, 256), 256>>>(rel[g]);

        k_transe<<<nblk((long)2 * TT * 32, 256), 256>>>(hI[g], tI[g], rI[g],
                                                        out_tv + (size_t)g * 2 * TT, 2 * TT);
        k_rule<<<nblk((long)RRULE * 32, 256), 256>>>(rhI[g], rtI[g], rrI[g], prem[g],
                                                     out_tv + (size_t)g * 2 * TT, g,
                                                     out_rule + (size_t)g * RRULE);
        k_gather<<<nblk((long)BB * DIMF, 256), 256>>>(dat[g], out_feat[g]);
    }
    (void)in_sizes; (void)n_in; (void)out_size;
}

// round 3
// speedup vs baseline: 2.4478x; 1.4569x over previous
#include <cuda_runtime.h>
#include <math.h>

#define NN    50000
#define DIMF  128
#define NH    8
#define HD    16
#define EE    800000
#define NRELC 2000
#define TT    200000
#define RRULE 50000
#define BB    10000
#define NPB   8
#define TV_INV 0.029462782549439483f   // 1/(3*sqrt(128))

// ---------------- device scratch (static, no runtime allocation) -------------
// graph-major: [2][...]
__device__ __align__(16) float d_x[2 * NN * DIMF];
__device__ __align__(16) float d_h[2 * NN * DIMF];
__device__ float               d_asrc[2 * NN * NH];
__device__ float               d_adst[2 * NN * NH];
__device__ __align__(16) float d_feat[2 * NN * DIMF];
__device__ __align__(16) float d_gnorm[2 * NN * DIMF];
__device__ __align__(16) float d_rnorm[2 * NRELC * DIMF];
__device__ int d_cnt[2 * NN];
__device__ int d_off[2 * (NN + 1)];
__device__ int d_cur[2 * NN];
__device__ int d_csrc[2 * EE];

// ---------------- f32x2 packed helpers ---------------------------------------
__device__ __forceinline__ unsigned long long pack2(float x, float y) {
    unsigned long long r;
    asm("mov.b64 %0, {%1, %2};" : "=l"(r) : "f"(x), "f"(y));
    return r;
}
__device__ __forceinline__ void unpack2(unsigned long long v, float& x, float& y) {
    asm("mov.b64 {%0, %1}, %2;" : "=f"(x), "=f"(y) : "l"(v));
}
__device__ __forceinline__ unsigned long long fma2(unsigned long long a,
                                                   unsigned long long b,
                                                   unsigned long long c) {
    unsigned long long r;
    asm("fma.rn.f32x2 %0, %1, %2, %3;" : "=l"(r) : "l"(a), "l"(b), "l"(c));
    return r;
}

// ---------------- CSR build (batched over both graphs) -----------------------
__global__ void k_zero_cnt() {
    int i = blockIdx.x * blockDim.x + threadIdx.x;
    if (i < 2 * NN) d_cnt[i] = 0;
}
__global__ void k_hist(const int* __restrict__ dst0, const int* __restrict__ dst1) {
    int i = blockIdx.x * blockDim.x + threadIdx.x;
    if (i >= EE) return;
    int g = blockIdx.y;
    const int* dst = g ? dst1 : dst0;
    atomicAdd(&d_cnt[g * NN + dst[i]], 1);
}
// one block per graph; coalesced chunked block scan
__global__ void __launch_bounds__(1024) k_scan() {
    int g = blockIdx.x;
    int t = threadIdx.x;
    int lane = t & 31, wid = t >> 5;
    __shared__ int wsum[32];
    int run = 0;
    const int NCH = (NN + 1023) / 1024;
    for (int c = 0; c < NCH; c++) {
        int i = c * 1024 + t;
        int val = (i < NN) ? d_cnt[g * NN + i] : 0;
        int incl = val;
#pragma unroll
        for (int o = 1; o < 32; o <<= 1) {
            int u = __shfl_up_sync(0xffffffffu, incl, o);
            if (lane >= o) incl += u;
        }
        if (lane == 31) wsum[wid] = incl;
        __syncthreads();
        if (wid == 0) {
            int ws = wsum[lane];
#pragma unroll
            for (int o = 1; o < 32; o <<= 1) {
                int u = __shfl_up_sync(0xffffffffu, ws, o);
                if (lane >= o) ws += u;
            }
            wsum[lane] = ws;
        }
        __syncthreads();
        int wb = (wid > 0) ? wsum[wid - 1] : 0;
        int excl = run + wb + incl - val;
        if (i < NN) {
            d_off[g * (NN + 1) + i] = excl;
            d_cur[g * NN + i] = excl;
        }
        run += wsum[31];
        __syncthreads();
    }
    if (t == 0) d_off[g * (NN + 1) + NN] = EE;
}
__global__ void k_scatter(const int* __restrict__ e0, const int* __restrict__ e1) {
    int i = blockIdx.x * blockDim.x + threadIdx.x;
    if (i >= EE) return;
    int g = blockIdx.y;
    const int* edg = g ? e1 : e0;
    int s = edg[i];
    int d = edg[EE + i];
    int p = atomicAdd(&d_cur[g * NN + d], 1);
    d_csrc[g * EE + p] = s;
}

// ---- GEMM: h = x @ W, 8 nodes per block, f32x2 packed accumulation ----
__global__ void __launch_bounds__(128) k_gemm8(const float* __restrict__ x0,
                                               const float* __restrict__ x1,
                                               const float* __restrict__ W,
                                               int layer0) {
    __shared__ __align__(16) float xst[DIMF][NPB];   // transposed: [d][node]
    int g = blockIdx.y;
    const float* xsrc = layer0 ? (g ? x1 : x0) : (d_x + (size_t)g * NN * DIMF);
    int nb = blockIdx.x * NPB;
    int t = threadIdx.x;

    for (int k = t; k < NPB * DIMF; k += 128) {
        int u = k >> 7, d = k & 127;
        xst[d][u] = xsrc[(size_t)(nb + u) * DIMF + d];
    }
    __syncthreads();

    unsigned long long a01 = 0ull, a23 = 0ull, a45 = 0ull, a67 = 0ull;
#pragma unroll 8
    for (int d = 0; d < DIMF; d++) {
        float w = __ldg(W + d * DIMF + t);
        unsigned long long w2 = pack2(w, w);
        const ulonglong2* xr = reinterpret_cast<const ulonglong2*>(&xst[d][0]);
        ulonglong2 p0 = xr[0];
        ulonglong2 p1 = xr[1];
        a01 = fma2(p0.x, w2, a01);
        a23 = fma2(p0.y, w2, a23);
        a45 = fma2(p1.x, w2, a45);
        a67 = fma2(p1.y, w2, a67);
    }
    float v[NPB];
    unpack2(a01, v[0], v[1]);
    unpack2(a23, v[2], v[3]);
    unpack2(a45, v[4], v[5]);
    unpack2(a67, v[6], v[7]);
    float* hb = d_h + (size_t)g * NN * DIMF;
#pragma unroll
    for (int u = 0; u < NPB; u++)
        hb[(size_t)(nb + u) * DIMF + t] = v[u];
}

// ---- attention scalars: warp per node ----
__global__ void __launch_bounds__(256) k_alpha(const float* __restrict__ a_s,
                                               const float* __restrict__ a_d) {
    int gt = blockIdx.x * blockDim.x + threadIdx.x;
    int n = gt >> 5, lane = gt & 31;
    if (n >= NN) return;
    int g = blockIdx.y;
    const float* hb = d_h + (size_t)g * NN * DIMF;
    float4 h4 = reinterpret_cast<const float4*>(hb + (size_t)n * DIMF)[lane];
    float4 as = reinterpret_cast<const float4*>(a_s)[lane];
    float4 ad = reinterpret_cast<const float4*>(a_d)[lane];
    float v1 = h4.x * as.x + h4.y * as.y + h4.z * as.z + h4.w * as.w;
    float v2 = h4.x * ad.x + h4.y * ad.y + h4.z * ad.z + h4.w * ad.w;
    v1 += __shfl_down_sync(0xffffffffu, v1, 2, 4);
    v2 += __shfl_down_sync(0xffffffffu, v2, 2, 4);
    v1 += __shfl_down_sync(0xffffffffu, v1, 1, 4);
    v2 += __shfl_down_sync(0xffffffffu, v2, 1, 4);
    if ((lane & 3) == 0) {
        int head = lane >> 2;
        d_asrc[(size_t)g * NN * NH + n * NH + head] = v1;
        d_adst[(size_t)g * NN * NH + n * NH + head] = v2;
    }
}

// ---- fused softmax-aggregate: warp per dst node, single pass, no atomics ----
// softmax is shift-invariant; logits are O(1) so exp() without max is safe.
__global__ void __launch_bounds__(256) k_agg(int last) {
    int gt = blockIdx.x * blockDim.x + threadIdx.x;
    int n = gt >> 5, lane = gt & 31;
    if (n >= NN) return;
    int g = blockIdx.y;
    const int* off = d_off + g * (NN + 1);
    const int* csrc = d_csrc + (size_t)g * EE;
    const float* hb = d_h + (size_t)g * NN * DIMF;
    const float* asb = d_asrc + (size_t)g * NN * NH;
    int head = lane >> 2;

    float adst_l = d_adst[(size_t)g * NN * NH + n * NH + head];

    int beg = off[n], end = off[n + 1];
    float4 acc = make_float4(0.f, 0.f, 0.f, 0.f);
    float den = 0.0f;
    int s = (beg < end) ? __ldg(&csrc[beg]) : 0;
    for (int j = beg; j < end; j++) {
        int snext = (j + 1 < end) ? __ldg(&csrc[j + 1]) : 0;
        float v = __ldg(&asb[s * NH + head]) + adst_l;
        v = fmaxf(v, 0.2f * v);          // leaky_relu(0.2)
        float w = __expf(v) ;
        // use accurate expf to stay bit-close to reference
        w = expf(v);
        den += w;
        float4 hv = reinterpret_cast<const float4*>(hb + (size_t)s * DIMF)[lane];
        acc.x = fmaf(w, hv.x, acc.x);
        acc.y = fmaf(w, hv.y, acc.y);
        acc.z = fmaf(w, hv.z, acc.z);
        acc.w = fmaf(w, hv.w, acc.w);
        s = snext;
    }
    float inv = 1.0f / fmaxf(den, 1e-16f);
    acc.x *= inv; acc.y *= inv; acc.z *= inv; acc.w *= inv;

    if (last) {
        reinterpret_cast<float4*>(d_feat + (size_t)g * NN * DIMF +
                                  (size_t)n * DIMF)[lane] = acc;
        // fused l2 norm
        float s2 = acc.x * acc.x + acc.y * acc.y + acc.z * acc.z + acc.w * acc.w;
#pragma unroll
        for (int o = 16; o > 0; o >>= 1) s2 += __shfl_xor_sync(0xffffffffu, s2, o);
        float sc = 1.0f / fmaxf(sqrtf(s2), 1e-12f);
        float4 nv = make_float4(acc.x * sc, acc.y * sc, acc.z * sc, acc.w * sc);
        reinterpret_cast<float4*>(d_gnorm + (size_t)g * NN * DIMF +
                                  (size_t)n * DIMF)[lane] = nv;
    } else {
        acc.x = (acc.x > 0.f) ? acc.x : expm1f(acc.x);
        acc.y = (acc.y > 0.f) ? acc.y : expm1f(acc.y);
        acc.z = (acc.z > 0.f) ? acc.z : expm1f(acc.z);
        acc.w = (acc.w > 0.f) ? acc.w : expm1f(acc.w);
        reinterpret_cast<float4*>(d_x + (size_t)g * NN * DIMF +
                                  (size_t)n * DIMF)[lane] = acc;
    }
}

__global__ void k_norm_rel(const float* __restrict__ rel0,
                           const float* __restrict__ rel1) {
    int gt = blockIdx.x * blockDim.x + threadIdx.x;
    int row = gt >> 5, lane = gt & 31;
    if (row >= NRELC) return;
    int g = blockIdx.y;
    const float* rel = g ? rel1 : rel0;
    float4 v = reinterpret_cast<const float4*>(rel + (size_t)row * DIMF)[lane];
    float s = v.x * v.x + v.y * v.y + v.z * v.z + v.w * v.w;
#pragma unroll
    for (int o = 16; o > 0; o >>= 1) s += __shfl_xor_sync(0xffffffffu, s, o);
    float sc = 1.0f / fmaxf(sqrtf(s), 1e-12f);
    v.x *= sc; v.y *= sc; v.z *= sc; v.w *= sc;
    reinterpret_cast<float4*>(d_rnorm + (size_t)g * NRELC * DIMF +
                              (size_t)row * DIMF)[lane] = v;
}

__device__ __forceinline__ float transe_tv_warp(const float* gn, const float* rn,
                                                int hh, int tt, int rr, int lane) {
    float4 a = reinterpret_cast<const float4*>(gn + (size_t)hh * DIMF)[lane];
    float4 b = reinterpret_cast<const float4*>(rn + (size_t)rr * DIMF)[lane];
    float4 c = reinterpret_cast<const float4*>(gn + (size_t)tt * DIMF)[lane];
    float s = fabsf(a.x + b.x - c.x) + fabsf(a.y + b.y - c.y) +
              fabsf(a.z + b.z - c.z) + fabsf(a.w + b.w - c.w);
#pragma unroll
    for (int o = 16; o > 0; o >>= 1) s += __shfl_down_sync(0xffffffffu, s, o);
    return 1.0f - s * TV_INV;
}

__global__ void __launch_bounds__(256) k_transe(const int* __restrict__ h0,
                                                const int* __restrict__ h1,
                                                const int* __restrict__ t0,
                                                const int* __restrict__ t1,
                                                const int* __restrict__ r0,
                                                const int* __restrict__ r1,
                                                float* __restrict__ out) {
    int gt = blockIdx.x * blockDim.x + threadIdx.x;
    int w = gt >> 5, lane = gt & 31;
    if (w >= 2 * TT) return;
    int g = blockIdx.y;
    const int* hI = g ? h1 : h0;
    const int* tI = g ? t1 : t0;
    const int* rI = g ? r1 : r0;
    const float* gn = d_gnorm + (size_t)g * NN * DIMF;
    const float* rn = d_rnorm + (size_t)g * NRELC * DIMF;
    float tv = transe_tv_warp(gn, rn, hI[w], tI[w], rI[w], lane);
    if (lane == 0) out[(size_t)g * 2 * TT + w] = tv;
}

__global__ void __launch_bounds__(256) k_rule(const int* __restrict__ rh0,
                                              const int* __restrict__ rh1,
                                              const int* __restrict__ rt0,
                                              const int* __restrict__ rt1,
                                              const int* __restrict__ rr0,
                                              const int* __restrict__ rr1,
                                              const int* __restrict__ pm0,
                                              const int* __restrict__ pm1,
                                              const float* __restrict__ tvbase,
                                              float* __restrict__ out) {
    int gt = blockIdx.x * blockDim.x + threadIdx.x;
    int w = gt >> 5, lane = gt & 31;
    if (w >= RRULE) return;
    int g = blockIdx.y;
    const int* rh = g ? rh1 : rh0;
    const int* rt = g ? rt1 : rt0;
    const int* rr = g ? rr1 : rr0;
    const int* prem = g ? pm1 : pm0;
    const float* gn = d_gnorm + (size_t)g * NN * DIMF;
    const float* rn = d_rnorm + (size_t)g * NRELC * DIMF;
    const float* tv = tvbase + (size_t)g * 2 * TT;
    float rs = transe_tv_warp(gn, rn, rh[w], rt[w], rr[w], lane);
    if (lane == 0) {
        int p0 = prem[w * 2 + 0];
        int p1 = prem[w * 2 + 1];
        float f1 = (p0 < TT) ? tv[p0 * 2 + g] : 1.0f;
        float f2 = (p1 < TT) ? tv[p1 * 2 + g] : 1.0f;
        out[(size_t)g * RRULE + w] = 1.0f + f1 * f2 * (rs - 1.0f);
    }
}

__global__ void k_gather(const int* __restrict__ i0, const int* __restrict__ i1,
                         float* __restrict__ out) {
    int i = blockIdx.x * blockDim.x + threadIdx.x;
    if (i >= BB * DIMF) return;
    int g = blockIdx.y;
    const int* idx = g ? i1 : i0;
    int b = i >> 7, c = i & 127;
    out[(size_t)g * BB * DIMF + i] =
        d_feat[(size_t)g * NN * DIMF + (size_t)idx[b] * DIMF + c];
}

// ---------------- host orchestration ----------------------------------------
static inline int nblk(long n, int t) { return (int)((n + t - 1) / t); }

extern "C" void kernel_launch(void* const* d_in, const int* in_sizes, int n_in,
                              void* d_out, int out_size) {
    const float* ent0 = (const float*)d_in[0];
    const float* ent1 = (const float*)d_in[1];
    const float* rel0 = (const float*)d_in[2];
    const float* rel1 = (const float*)d_in[3];
    const float* W    = (const float*)d_in[4];
    const float* a_s  = (const float*)d_in[5];
    const float* a_d  = (const float*)d_in[6];
    const int* dat0 = (const int*)d_in[7];
    const int* dat1 = (const int*)d_in[8];
    const int* edg0 = (const int*)d_in[9];
    const int* edg1 = (const int*)d_in[10];
    const int* h0 = (const int*)d_in[11];
    const int* t0 = (const int*)d_in[12];
    const int* r0 = (const int*)d_in[13];
    const int* h1 = (const int*)d_in[14];
    const int* t1 = (const int*)d_in[15];
    const int* r1 = (const int*)d_in[16];
    const int* rh0 = (const int*)d_in[17];
    const int* rt0 = (const int*)d_in[18];
    const int* rr0 = (const int*)d_in[19];
    const int* pm0 = (const int*)d_in[20];
    const int* rh1 = (const int*)d_in[21];
    const int* rt1 = (const int*)d_in[22];
    const int* rr1 = (const int*)d_in[23];
    const int* pm1 = (const int*)d_in[24];

    float* out      = (float*)d_out;
    float* out_feat = out;                                   // [2][B,128]
    float* out_tv   = out + 2 * (size_t)BB * DIMF;           // [2][2T]
    float* out_rule = out_tv + 4 * (size_t)TT;               // [2][R]

    dim3 g2;

    // CSR build for both graphs
    k_zero_cnt<<<nblk(2 * NN, 256), 256>>>();
    g2 = dim3(nblk(EE, 256), 2);
    k_hist<<<g2, 256>>>(edg0 + EE, edg1 + EE);
    k_scan<<<2, 1024>>>();
    k_scatter<<<g2, 256>>>(edg0, edg1);

    for (int l = 0; l < 2; l++) {
        g2 = dim3(NN / NPB, 2);
        k_gemm8<<<g2, 128>>>(ent0, ent1, W + (size_t)l * DIMF * DIMF, l == 0);
        g2 = dim3(nblk((long)NN * 32, 256), 2);
        k_alpha<<<g2, 256>>>(a_s + (size_t)l * DIMF, a_d + (size_t)l * DIMF);
        k_agg<<<g2, 256>>>(l == 1 ? 1 : 0);
    }

    g2 = dim3(nblk((long)NRELC * 32, 256), 2);
    k_norm_rel<<<g2, 256>>>(rel0, rel1);

    g2 = dim3(nblk((long)2 * TT * 32, 256), 2);
    k_transe<<<g2, 256>>>(h0, h1, t0, t1, r0, r1, out_tv);

    g2 = dim3(nblk((long)RRULE * 32, 256), 2);
    k_rule<<<g2, 256>>>(rh0, rh1, rt0, rt1, rr0, rr1, pm0, pm1, out_tv, out_rule);

    g2 = dim3(nblk((long)BB * DIMF, 256), 2);
    k_gather<<<g2, 256>>>(dat0, dat1, out_feat);

    (void)in_sizes; (void)n_in; (void)out_size;
}

// round 4
// speedup vs baseline: 2.5297x; 1.0335x over previous
#include <cuda_runtime.h>
#include <math.h>

#define NN    50000
#define DIMF  128
#define NH    8
#define HD    16
#define EE    800000
#define NRELC 2000
#define TT    200000
#define RRULE 50000
#define BB    10000
#define NPB   16
#define TV_INV 0.029462782549439483f   // 1/(3*sqrt(128))

// ---------------- device scratch (static, no runtime allocation) -------------
__device__ __align__(16) float d_x[2 * NN * DIMF];
__device__ __align__(16) float d_h[2 * NN * DIMF];
__device__ float               d_asrc[2 * NN * NH];
__device__ float               d_adst[2 * NN * NH];
__device__ __align__(16) float d_feat[2 * NN * DIMF];
__device__ __align__(16) float d_gnorm[2 * NN * DIMF];
__device__ __align__(16) float d_rnorm[2 * NRELC * DIMF];
__device__ int d_cnt[2 * NN];
__device__ int d_off[2 * (NN + 1)];
__device__ int d_cur[2 * NN];
__device__ int d_csrc[2 * EE];

// ---------------- f32x2 packed helpers ---------------------------------------
__device__ __forceinline__ unsigned long long pack2(float x, float y) {
    unsigned long long r;
    asm("mov.b64 %0, {%1, %2};" : "=l"(r) : "f"(x), "f"(y));
    return r;
}
__device__ __forceinline__ void unpack2(unsigned long long v, float& x, float& y) {
    asm("mov.b64 {%0, %1}, %2;" : "=f"(x), "=f"(y) : "l"(v));
}
__device__ __forceinline__ unsigned long long fma2(unsigned long long a,
                                                   unsigned long long b,
                                                   unsigned long long c) {
    unsigned long long r;
    asm("fma.rn.f32x2 %0, %1, %2, %3;" : "=l"(r) : "l"(a), "l"(b), "l"(c));
    return r;
}

// ---------------- CSR build (batched over both graphs) -----------------------
__global__ void k_zero_cnt() {
    int i = blockIdx.x * blockDim.x + threadIdx.x;
    if (i < 2 * NN) d_cnt[i] = 0;
}
__global__ void k_hist(const int* __restrict__ dst0, const int* __restrict__ dst1) {
    int i = blockIdx.x * blockDim.x + threadIdx.x;
    if (i >= EE) return;
    int g = blockIdx.y;
    const int* dst = g ? dst1 : dst0;
    atomicAdd(&d_cnt[g * NN + dst[i]], 1);
}
__global__ void __launch_bounds__(1024) k_scan() {
    int g = blockIdx.x;
    int t = threadIdx.x;
    int lane = t & 31, wid = t >> 5;
    __shared__ int wsum[32];
    int run = 0;
    const int NCH = (NN + 1023) / 1024;
    for (int c = 0; c < NCH; c++) {
        int i = c * 1024 + t;
        int val = (i < NN) ? d_cnt[g * NN + i] : 0;
        int incl = val;
#pragma unroll
        for (int o = 1; o < 32; o <<= 1) {
            int u = __shfl_up_sync(0xffffffffu, incl, o);
            if (lane >= o) incl += u;
        }
        if (lane == 31) wsum[wid] = incl;
        __syncthreads();
        if (wid == 0) {
            int ws = wsum[lane];
#pragma unroll
            for (int o = 1; o < 32; o <<= 1) {
                int u = __shfl_up_sync(0xffffffffu, ws, o);
                if (lane >= o) ws += u;
            }
            wsum[lane] = ws;
        }
        __syncthreads();
        int wb = (wid > 0) ? wsum[wid - 1] : 0;
        int excl = run + wb + incl - val;
        if (i < NN) {
            d_off[g * (NN + 1) + i] = excl;
            d_cur[g * NN + i] = excl;
        }
        run += wsum[31];
        __syncthreads();
    }
    if (t == 0) d_off[g * (NN + 1) + NN] = EE;
}
__global__ void k_scatter(const int* __restrict__ e0, const int* __restrict__ e1) {
    int i = blockIdx.x * blockDim.x + threadIdx.x;
    if (i >= EE) return;
    int g = blockIdx.y;
    const int* edg = g ? e1 : e0;
    int s = edg[i];
    int d = edg[EE + i];
    int p = atomicAdd(&d_cur[g * NN + d], 1);
    d_csrc[g * EE + p] = s;
}

// ---- GEMM: h = x @ W, 16 nodes per block, f32x2 packed accumulation ----
__global__ void __launch_bounds__(128) k_gemm16(const float* __restrict__ x0,
                                                const float* __restrict__ x1,
                                                const float* __restrict__ W,
                                                int layer0) {
    __shared__ __align__(16) float xst[DIMF][NPB];   // transposed: [d][node]
    int g = blockIdx.y;
    const float* xsrc = layer0 ? (g ? x1 : x0) : (d_x + (size_t)g * NN * DIMF);
    int nb = blockIdx.x * NPB;
    int t = threadIdx.x;

    for (int k = t; k < NPB * DIMF; k += 128) {
        int u = k >> 7, d = k & 127;
        xst[d][u] = xsrc[(size_t)(nb + u) * DIMF + d];
    }
    __syncthreads();

    unsigned long long a[NPB / 2];
#pragma unroll
    for (int q = 0; q < NPB / 2; q++) a[q] = 0ull;

#pragma unroll 4
    for (int d = 0; d < DIMF; d++) {
        float w = __ldg(W + d * DIMF + t);
        unsigned long long w2 = pack2(w, w);
        const ulonglong2* xr = reinterpret_cast<const ulonglong2*>(&xst[d][0]);
#pragma unroll
        for (int q = 0; q < NPB / 4; q++) {
            ulonglong2 p = xr[q];
            a[2 * q]     = fma2(p.x, w2, a[2 * q]);
            a[2 * q + 1] = fma2(p.y, w2, a[2 * q + 1]);
        }
    }
    float v[NPB];
#pragma unroll
    for (int q = 0; q < NPB / 2; q++) unpack2(a[q], v[2 * q], v[2 * q + 1]);
    float* hb = d_h + (size_t)g * NN * DIMF;
#pragma unroll
    for (int u = 0; u < NPB; u++)
        hb[(size_t)(nb + u) * DIMF + t] = v[u];
}

// ---- attention scalars: warp per node ----
__global__ void __launch_bounds__(256) k_alpha(const float* __restrict__ a_s,
                                               const float* __restrict__ a_d) {
    int gt = blockIdx.x * blockDim.x + threadIdx.x;
    int n = gt >> 5, lane = gt & 31;
    if (n >= NN) return;
    int g = blockIdx.y;
    const float* hb = d_h + (size_t)g * NN * DIMF;
    float4 h4 = reinterpret_cast<const float4*>(hb + (size_t)n * DIMF)[lane];
    float4 as = reinterpret_cast<const float4*>(a_s)[lane];
    float4 ad = reinterpret_cast<const float4*>(a_d)[lane];
    float v1 = h4.x * as.x + h4.y * as.y + h4.z * as.z + h4.w * as.w;
    float v2 = h4.x * ad.x + h4.y * ad.y + h4.z * ad.z + h4.w * ad.w;
    v1 += __shfl_down_sync(0xffffffffu, v1, 2, 4);
    v2 += __shfl_down_sync(0xffffffffu, v2, 2, 4);
    v1 += __shfl_down_sync(0xffffffffu, v1, 1, 4);
    v2 += __shfl_down_sync(0xffffffffu, v2, 1, 4);
    if ((lane & 3) == 0) {
        int head = lane >> 2;
        d_asrc[(size_t)g * NN * NH + n * NH + head] = v1;
        d_adst[(size_t)g * NN * NH + n * NH + head] = v2;
    }
}

// ---- fused softmax-aggregate: warp per dst node, single pass, no atomics ----
// softmax is shift-invariant; logits are O(1) so exp() without max is safe.
__global__ void __launch_bounds__(256) k_agg(int last) {
    int gt = blockIdx.x * blockDim.x + threadIdx.x;
    int n = gt >> 5, lane = gt & 31;
    if (n >= NN) return;
    int g = blockIdx.y;
    const int* off = d_off + g * (NN + 1);
    const int* csrc = d_csrc + (size_t)g * EE;
    const float* hb = d_h + (size_t)g * NN * DIMF;
    const float* asb = d_asrc + (size_t)g * NN * NH;
    int head = lane >> 2;

    float adst_l = d_adst[(size_t)g * NN * NH + n * NH + head];

    int beg = off[n], end = off[n + 1];
    float4 acc = make_float4(0.f, 0.f, 0.f, 0.f);
    float den = 0.0f;

    int j = beg;
    // 2-edge unrolled main loop: issue all loads for both edges up front
    for (; j + 2 <= end; j += 2) {
        int s0 = __ldg(&csrc[j]);
        int s1 = __ldg(&csrc[j + 1]);
        float al0 = __ldg(&asb[s0 * NH + head]);
        float al1 = __ldg(&asb[s1 * NH + head]);
        float4 h0 = reinterpret_cast<const float4*>(hb + (size_t)s0 * DIMF)[lane];
        float4 h1 = reinterpret_cast<const float4*>(hb + (size_t)s1 * DIMF)[lane];
        float v0 = al0 + adst_l; v0 = fmaxf(v0, 0.2f * v0);
        float v1 = al1 + adst_l; v1 = fmaxf(v1, 0.2f * v1);
        float w0 = __expf(v0);
        float w1 = __expf(v1);
        den += w0 + w1;
        acc.x = fmaf(w0, h0.x, fmaf(w1, h1.x, acc.x));
        acc.y = fmaf(w0, h0.y, fmaf(w1, h1.y, acc.y));
        acc.z = fmaf(w0, h0.z, fmaf(w1, h1.z, acc.z));
        acc.w = fmaf(w0, h0.w, fmaf(w1, h1.w, acc.w));
    }
    if (j < end) {
        int s0 = __ldg(&csrc[j]);
        float al0 = __ldg(&asb[s0 * NH + head]);
        float4 h0 = reinterpret_cast<const float4*>(hb + (size_t)s0 * DIMF)[lane];
        float v0 = al0 + adst_l; v0 = fmaxf(v0, 0.2f * v0);
        float w0 = __expf(v0);
        den += w0;
        acc.x = fmaf(w0, h0.x, acc.x);
        acc.y = fmaf(w0, h0.y, acc.y);
        acc.z = fmaf(w0, h0.z, acc.z);
        acc.w = fmaf(w0, h0.w, acc.w);
    }

    float inv = 1.0f / fmaxf(den, 1e-16f);
    acc.x *= inv; acc.y *= inv; acc.z *= inv; acc.w *= inv;

    if (last) {
        reinterpret_cast<float4*>(d_feat + (size_t)g * NN * DIMF +
                                  (size_t)n * DIMF)[lane] = acc;
        float s2 = acc.x * acc.x + acc.y * acc.y + acc.z * acc.z + acc.w * acc.w;
#pragma unroll
        for (int o = 16; o > 0; o >>= 1) s2 += __shfl_xor_sync(0xffffffffu, s2, o);
        float sc = 1.0f / fmaxf(sqrtf(s2), 1e-12f);
        float4 nv = make_float4(acc.x * sc, acc.y * sc, acc.z * sc, acc.w * sc);
        reinterpret_cast<float4*>(d_gnorm + (size_t)g * NN * DIMF +
                                  (size_t)n * DIMF)[lane] = nv;
    } else {
        acc.x = (acc.x > 0.f) ? acc.x : expm1f(acc.x);
        acc.y = (acc.y > 0.f) ? acc.y : expm1f(acc.y);
        acc.z = (acc.z > 0.f) ? acc.z : expm1f(acc.z);
        acc.w = (acc.w > 0.f) ? acc.w : expm1f(acc.w);
        reinterpret_cast<float4*>(d_x + (size_t)g * NN * DIMF +
                                  (size_t)n * DIMF)[lane] = acc;
    }
}

__global__ void k_norm_rel(const float* __restrict__ rel0,
                           const float* __restrict__ rel1) {
    int gt = blockIdx.x * blockDim.x + threadIdx.x;
    int row = gt >> 5, lane = gt & 31;
    if (row >= NRELC) return;
    int g = blockIdx.y;
    const float* rel = g ? rel1 : rel0;
    float4 v = reinterpret_cast<const float4*>(rel + (size_t)row * DIMF)[lane];
    float s = v.x * v.x + v.y * v.y + v.z * v.z + v.w * v.w;
#pragma unroll
    for (int o = 16; o > 0; o >>= 1) s += __shfl_xor_sync(0xffffffffu, s, o);
    float sc = 1.0f / fmaxf(sqrtf(s), 1e-12f);
    v.x *= sc; v.y *= sc; v.z *= sc; v.w *= sc;
    reinterpret_cast<float4*>(d_rnorm + (size_t)g * NRELC * DIMF +
                              (size_t)row * DIMF)[lane] = v;
}

__device__ __forceinline__ float transe_tv_warp(const float* gn, const float* rn,
                                                int hh, int tt, int rr, int lane) {
    float4 a = reinterpret_cast<const float4*>(gn + (size_t)hh * DIMF)[lane];
    float4 b = reinterpret_cast<const float4*>(rn + (size_t)rr * DIMF)[lane];
    float4 c = reinterpret_cast<const float4*>(gn + (size_t)tt * DIMF)[lane];
    float s = fabsf(a.x + b.x - c.x) + fabsf(a.y + b.y - c.y) +
              fabsf(a.z + b.z - c.z) + fabsf(a.w + b.w - c.w);
#pragma unroll
    for (int o = 16; o > 0; o >>= 1) s += __shfl_down_sync(0xffffffffu, s, o);
    return 1.0f - s * TV_INV;
}

__global__ void __launch_bounds__(256) k_transe(const int* __restrict__ h0,
                                                const int* __restrict__ h1,
                                                const int* __restrict__ t0,
                                                const int* __restrict__ t1,
                                                const int* __restrict__ r0,
                                                const int* __restrict__ r1,
                                                float* __restrict__ out) {
    int gt = blockIdx.x * blockDim.x + threadIdx.x;
    int w = gt >> 5, lane = gt & 31;
    if (w >= 2 * TT) return;
    int g = blockIdx.y;
    const int* hI = g ? h1 : h0;
    const int* tI = g ? t1 : t0;
    const int* rI = g ? r1 : r0;
    const float* gn = d_gnorm + (size_t)g * NN * DIMF;
    const float* rn = d_rnorm + (size_t)g * NRELC * DIMF;
    float tv = transe_tv_warp(gn, rn, hI[w], tI[w], rI[w], lane);
    if (lane == 0) out[(size_t)g * 2 * TT + w] = tv;
}

__global__ void __launch_bounds__(256) k_rule(const int* __restrict__ rh0,
                                              const int* __restrict__ rh1,
                                              const int* __restrict__ rt0,
                                              const int* __restrict__ rt1,
                                              const int* __restrict__ rr0,
                                              const int* __restrict__ rr1,
                                              const int* __restrict__ pm0,
                                              const int* __restrict__ pm1,
                                              const float* __restrict__ tvbase,
                                              float* __restrict__ out) {
    int gt = blockIdx.x * blockDim.x + threadIdx.x;
    int w = gt >> 5, lane = gt & 31;
    if (w >= RRULE) return;
    int g = blockIdx.y;
    const int* rh = g ? rh1 : rh0;
    const int* rt = g ? rt1 : rt0;
    const int* rr = g ? rr1 : rr0;
    const int* prem = g ? pm1 : pm0;
    const float* gn = d_gnorm + (size_t)g * NN * DIMF;
    const float* rn = d_rnorm + (size_t)g * NRELC * DIMF;
    const float* tv = tvbase + (size_t)g * 2 * TT;
    float rs = transe_tv_warp(gn, rn, rh[w], rt[w], rr[w], lane);
    if (lane == 0) {
        int p0 = prem[w * 2 + 0];
        int p1 = prem[w * 2 + 1];
        float f1 = (p0 < TT) ? tv[p0 * 2 + g] : 1.0f;
        float f2 = (p1 < TT) ? tv[p1 * 2 + g] : 1.0f;
        out[(size_t)g * RRULE + w] = 1.0f + f1 * f2 * (rs - 1.0f);
    }
}

__global__ void k_gather(const int* __restrict__ i0, const int* __restrict__ i1,
                         float* __restrict__ out) {
    int i = blockIdx.x * blockDim.x + threadIdx.x;
    if (i >= BB * DIMF) return;
    int g = blockIdx.y;
    const int* idx = g ? i1 : i0;
    int b = i >> 7, c = i & 127;
    out[(size_t)g * BB * DIMF + i] =
        d_feat[(size_t)g * NN * DIMF + (size_t)idx[b] * DIMF + c];
}

// ---------------- host orchestration ----------------------------------------
static inline int nblk(long n, int t) { return (int)((n + t - 1) / t); }

extern "C" void kernel_launch(void* const* d_in, const int* in_sizes, int n_in,
                              void* d_out, int out_size) {
    const float* ent0 = (const float*)d_in[0];
    const float* ent1 = (const float*)d_in[1];
    const float* rel0 = (const float*)d_in[2];
    const float* rel1 = (const float*)d_in[3];
    const float* W    = (const float*)d_in[4];
    const float* a_s  = (const float*)d_in[5];
    const float* a_d  = (const float*)d_in[6];
    const int* dat0 = (const int*)d_in[7];
    const int* dat1 = (const int*)d_in[8];
    const int* edg0 = (const int*)d_in[9];
    const int* edg1 = (const int*)d_in[10];
    const int* h0 = (const int*)d_in[11];
    const int* t0 = (const int*)d_in[12];
    const int* r0 = (const int*)d_in[13];
    const int* h1 = (const int*)d_in[14];
    const int* t1 = (const int*)d_in[15];
    const int* r1 = (const int*)d_in[16];
    const int* rh0 = (const int*)d_in[17];
    const int* rt0 = (const int*)d_in[18];
    const int* rr0 = (const int*)d_in[19];
    const int* pm0 = (const int*)d_in[20];
    const int* rh1 = (const int*)d_in[21];
    const int* rt1 = (const int*)d_in[22];
    const int* rr1 = (const int*)d_in[23];
    const int* pm1 = (const int*)d_in[24];

    float* out      = (float*)d_out;
    float* out_feat = out;
    float* out_tv   = out + 2 * (size_t)BB * DIMF;
    float* out_rule = out_tv + 4 * (size_t)TT;

    dim3 g2;

    k_zero_cnt<<<nblk(2 * NN, 256), 256>>>();
    g2 = dim3(nblk(EE, 256), 2);
    k_hist<<<g2, 256>>>(edg0 + EE, edg1 + EE);
    k_scan<<<2, 1024>>>();
    k_scatter<<<g2, 256>>>(edg0, edg1);

    for (int l = 0; l < 2; l++) {
        g2 = dim3(NN / NPB, 2);
        k_gemm16<<<g2, 128>>>(ent0, ent1, W + (size_t)l * DIMF * DIMF, l == 0);
        g2 = dim3(nblk((long)NN * 32, 256), 2);
        k_alpha<<<g2, 256>>>(a_s + (size_t)l * DIMF, a_d + (size_t)l * DIMF);
        k_agg<<<g2, 256>>>(l == 1 ? 1 : 0);
    }

    g2 = dim3(nblk((long)NRELC * 32, 256), 2);
    k_norm_rel<<<g2, 256>>>(rel0, rel1);

    g2 = dim3(nblk((long)2 * TT * 32, 256), 2);
    k_transe<<<g2, 256>>>(h0, h1, t0, t1, r0, r1, out_tv);

    g2 = dim3(nblk((long)RRULE * 32, 256), 2);
    k_rule<<<g2, 256>>>(rh0, rh1, rt0, rt1, rr0, rr1, pm0, pm1, out_tv, out_rule);

    g2 = dim3(nblk((long)BB * DIMF, 256), 2);
    k_gather<<<g2, 256>>>(dat0, dat1, out_feat);

    (void)in_sizes; (void)n_in; (void)out_size;
}